// round 4
// baseline (speedup 1.0000x reference)
#include <cuda_runtime.h>
#include <cuda_bf16.h>
#include <math.h>
#include <stdint.h>

#define H        512
#define NDRONES  16384
#define NPAIRS   131072

#define NCH      8          // K chunks of 64
#define A_TILE   32768      // 128 rows x 64 k x bf16 (hi 16K + lo 16K)
#define B_TILE   65536      // 256 rows x 64 k x bf16 (hi 32K + lo 32K)
#define STAGE    98304      // A_TILE + B_TILE

// ---------------- device scratch ---------------------------------------------
__device__ __align__(128) char g_P [(size_t)1024 * NCH * A_TILE]; // pair product tiles (256MB)
__device__ __align__(128) char g_ET[(size_t)128  * NCH * A_TILE]; // E split tiles (32MB)
__device__ __align__(128) char g_BP[(size_t)2 * NCH * B_TILE];    // W1d^T tiles
__device__ __align__(128) char g_BU[(size_t)4 * NCH * B_TILE];    // ABcomb^T tiles
__device__ float g_UV[(size_t)NDRONES * 2 * H];                   // [U(512)|V(512)] per drone
__device__ float g_partial[2 * NPAIRS];

// ---------------- helpers ----------------------------------------------------
__device__ __forceinline__ uint32_t smem_u32(const void* p) {
    uint32_t a;
    asm("{ .reg .u64 t; cvta.to.shared.u64 t, %1; cvt.u32.u64 %0, t; }" : "=r"(a) : "l"(p));
    return a;
}
#define SW128(o) ((o) ^ (((o) >> 3) & 0x70))

__device__ __forceinline__ void ldsm_x4(uint32_t* r, uint32_t addr) {
    asm volatile("ldmatrix.sync.aligned.m8n8.x4.shared.b16 {%0,%1,%2,%3}, [%4];"
        : "=r"(r[0]), "=r"(r[1]), "=r"(r[2]), "=r"(r[3]) : "r"(addr));
}
__device__ __forceinline__ void ldsm_x2(uint32_t* r, uint32_t addr) {
    asm volatile("ldmatrix.sync.aligned.m8n8.x2.shared.b16 {%0,%1}, [%2];"
        : "=r"(r[0]), "=r"(r[1]) : "r"(addr));
}
__device__ __forceinline__ void mma_bf16(float* c, const uint32_t* a, const uint32_t* b) {
    asm volatile("mma.sync.aligned.m16n8k16.row.col.f32.bf16.bf16.f32 "
        "{%0,%1,%2,%3}, {%4,%5,%6,%7}, {%8,%9}, {%0,%1,%2,%3};"
        : "+f"(c[0]), "+f"(c[1]), "+f"(c[2]), "+f"(c[3])
        : "r"(a[0]), "r"(a[1]), "r"(a[2]), "r"(a[3]), "r"(b[0]), "r"(b[1]));
}

#define MBARRIER_INIT(mbar, cnt) \
    asm volatile("mbarrier.init.shared.b64 [%0], %1;" :: "r"((uint32_t)(mbar)), "r"((uint32_t)(cnt)) : "memory")
#define MBARRIER_EXPECT_TX(mbar, tx) \
    asm volatile("mbarrier.arrive.expect_tx.shared.b64 _, [%0], %1;" :: "r"((uint32_t)(mbar)), "r"((uint32_t)(tx)) : "memory")
#define MBARRIER_WAIT_PARITY(mbar, parity) do { \
    uint32_t _m = (uint32_t)(mbar); uint32_t _p = (uint32_t)(parity); uint32_t _d; \
    asm volatile("{\n\t.reg .pred p;\n\tmbarrier.try_wait.parity.acquire.cta.shared::cta.b64 p, [%1], %2;\n\tselp.b32 %0,1,0,p;\n\t}" \
        : "=r"(_d) : "r"(_m), "r"(_p) : "memory"); \
    if (!_d) { \
        asm volatile("{\n\t.reg .pred P1;\n\tWL_%=:\n\tmbarrier.try_wait.parity.acquire.cta.shared::cta.b64 P1, [%0], %1, 0x989680;\n\t@P1 bra.uni WD_%=;\n\tbra.uni WL_%=;\n\tWD_%=:\n\t}" \
            :: "r"(_m), "r"(_p) : "memory"); \
    } } while (0)
#define FENCE_PROXY_ASYNC() asm volatile("fence.proxy.async.shared::cta;" ::: "memory")

__device__ __forceinline__ void bulk_g2s(uint32_t dst, const void* src, uint32_t bytes, uint32_t mbar) {
    asm volatile("cp.async.bulk.shared::cluster.global.mbarrier::complete_tx::bytes [%0], [%1], %2, [%3];"
        :: "r"(dst), "l"(src), "r"(bytes), "r"(mbar) : "memory");
}

// split 8 fp32 -> 4x bf16x2 hi + 4x bf16x2 lo
__device__ __forceinline__ void split8(const float* p, uint32_t* hi, uint32_t* lo) {
#pragma unroll
    for (int j = 0; j < 4; ++j) {
        float2 pp = make_float2(p[2 * j], p[2 * j + 1]);
        __nv_bfloat162 h2 = __float22bfloat162_rn(pp);
        float2 hf = __bfloat1622float2(h2);
        __nv_bfloat162 l2 = __float22bfloat162_rn(make_float2(pp.x - hf.x, pp.y - hf.y));
        hi[j] = *reinterpret_cast<uint32_t*>(&h2);
        lo[j] = *reinterpret_cast<uint32_t*>(&l2);
    }
}

// ---------------- SMEM layout for GEMM kernels -------------------------------
#define SM_MB    196608
#define SM_SRC   196640
#define SM_DST   197152
#define SM_B1    197664
#define SM_W2    198688
#define SMEM_GEMM 199744
#define CSTRIDE  260

// ---------------- shared GEMM mainloop ---------------------------------------
// CTA tile 128(M) x 256(N), K=512 in 8 chunks of 64. 8 warps, warp tile 64x64.
__device__ __forceinline__ void gemm_mainloop(
    uint32_t sb, const char* gA, const char* gB,
    float c[4][8][4], int t, int lane, int wm, int wn)
{
    if (t == 0) { MBARRIER_INIT(sb + SM_MB, 1); MBARRIER_INIT(sb + SM_MB + 8, 1); }
    __syncthreads();
    if (t == 0) {
#pragma unroll
        for (int s = 0; s < 2; ++s) {
            MBARRIER_EXPECT_TX(sb + SM_MB + s * 8, STAGE);
            bulk_g2s(sb + s * STAGE, gA + (size_t)s * A_TILE, A_TILE, sb + SM_MB + s * 8);
            bulk_g2s(sb + s * STAGE + A_TILE, gB + (size_t)s * B_TILE, B_TILE, sb + SM_MB + s * 8);
        }
    }

    uint32_t aoff[4], arx[4], boff[8], brx[8];
#pragma unroll
    for (int mt = 0; mt < 4; ++mt) {
        int rA = wm * 64 + mt * 16 + (lane & 15);
        aoff[mt] = rA * 128; arx[mt] = (rA & 7) * 16;
    }
#pragma unroll
    for (int nt = 0; nt < 8; ++nt) {
        int rB = wn * 64 + nt * 8 + (lane & 7);
        boff[nt] = rB * 128; brx[nt] = (rB & 7) * 16;
    }
    uint32_t selA = (lane >> 4) * 16;
    uint32_t selB = ((lane >> 3) & 1) * 16;

    int ph0 = 0, ph1 = 0;
    for (int ch = 0; ch < NCH; ++ch) {
        int s = ch & 1;
        if (s == 0) { MBARRIER_WAIT_PARITY(sb + SM_MB, ph0); ph0 ^= 1; }
        else        { MBARRIER_WAIT_PARITY(sb + SM_MB + 8, ph1); ph1 ^= 1; }

        uint32_t As = sb + s * STAGE;
        uint32_t Bs = As + A_TILE;
#pragma unroll
        for (int kh = 0; kh < 4; ++kh) {
            uint32_t kk = kh * 32;
            uint32_t ah[4][4], al[4][4];
#pragma unroll
            for (int mt = 0; mt < 4; ++mt) {
                uint32_t a = As + aoff[mt] + ((kk + selA) ^ arx[mt]);
                ldsm_x4(ah[mt], a);
                ldsm_x4(al[mt], a + 16384);
            }
#pragma unroll
            for (int nt = 0; nt < 8; ++nt) {
                uint32_t baddr = Bs + boff[nt] + ((kk + selB) ^ brx[nt]);
                uint32_t bh[2], bl[2];
                ldsm_x2(bh, baddr);
                ldsm_x2(bl, baddr + 32768);
#pragma unroll
                for (int mt = 0; mt < 4; ++mt) {
                    mma_bf16(c[mt][nt], ah[mt], bh);
                    mma_bf16(c[mt][nt], al[mt], bh);
                    mma_bf16(c[mt][nt], ah[mt], bl);
                }
            }
        }
        __syncthreads();
        if (t == 0 && ch + 2 < NCH) {
            FENCE_PROXY_ASYNC();
            MBARRIER_EXPECT_TX(sb + SM_MB + s * 8, STAGE);
            bulk_g2s(sb + s * STAGE, gA + (size_t)(ch + 2) * A_TILE, A_TILE, sb + SM_MB + s * 8);
            bulk_g2s(sb + s * STAGE + A_TILE, gB + (size_t)(ch + 2) * B_TILE, B_TILE, sb + SM_MB + s * 8);
        }
    }
}

__device__ __forceinline__ void c_to_smem(float* Cs, const float c[4][8][4], int lane, int wm, int wn) {
#pragma unroll
    for (int mt = 0; mt < 4; ++mt)
#pragma unroll
        for (int nt = 0; nt < 8; ++nt) {
            int r  = wm * 64 + mt * 16 + (lane >> 2);
            int c0 = wn * 64 + nt * 8 + (lane & 3) * 2;
            *(float2*)(Cs + r * CSTRIDE + c0)       = make_float2(c[mt][nt][0], c[mt][nt][1]);
            *(float2*)(Cs + (r + 8) * CSTRIDE + c0) = make_float2(c[mt][nt][2], c[mt][nt][3]);
        }
}

// ---------------- prep kernels -----------------------------------------------
__global__ void prep_BP(const float* __restrict__ W1) {
    extern __shared__ char bsm[];
    int t = threadIdx.x, ch = blockIdx.x, nb = blockIdx.y;
    int k0 = ch * 64, n0 = nb * 256;
#pragma unroll 4
    for (int i = 0; i < 64; ++i) {
        float v = W1[(size_t)(3 * H + k0 + i) * H + n0 + t];
        __nv_bfloat16 h = __float2bfloat16(v);
        __nv_bfloat16 l = __float2bfloat16(v - __bfloat162float(h));
        uint32_t off = SW128((uint32_t)(t * 128 + i * 2));
        *(__nv_bfloat16*)(bsm + off) = h;
        *(__nv_bfloat16*)(bsm + 32768 + off) = l;
    }
    __syncthreads();
    uint4* dst = (uint4*)(g_BP + ((size_t)nb * NCH + ch) * B_TILE);
    const uint4* s4 = (const uint4*)bsm;
#pragma unroll
    for (int j = 0; j < 16; ++j) dst[t * 16 + j] = s4[t * 16 + j];
}

__global__ void prep_BU(const float* __restrict__ W1) {
    extern __shared__ char bsm[];
    int t = threadIdx.x, ch = blockIdx.x, nb = blockIdx.y;
    int k0 = ch * 64;
    int ng = nb * 256 + t;
    bool isv = ng >= H;
    int nn = ng & (H - 1);
#pragma unroll 4
    for (int i = 0; i < 64; ++i) {
        int k = k0 + i;
        float wc = W1[(size_t)(2 * H + k) * H + nn];
        float v = isv ? (W1[(size_t)(H + k) * H + nn] + wc)
                      : (W1[(size_t)k * H + nn] - wc);
        __nv_bfloat16 h = __float2bfloat16(v);
        __nv_bfloat16 l = __float2bfloat16(v - __bfloat162float(h));
        uint32_t off = SW128((uint32_t)(t * 128 + i * 2));
        *(__nv_bfloat16*)(bsm + off) = h;
        *(__nv_bfloat16*)(bsm + 32768 + off) = l;
    }
    __syncthreads();
    uint4* dst = (uint4*)(g_BU + ((size_t)nb * NCH + ch) * B_TILE);
    const uint4* s4 = (const uint4*)bsm;
#pragma unroll
    for (int j = 0; j < 16; ++j) dst[t * 16 + j] = s4[t * 16 + j];
}

__global__ void prep_ET(const float* __restrict__ E) {
    __shared__ __align__(16) char esm[A_TILE];
    int t = threadIdx.x, ch = blockIdx.x, mb = blockIdx.y;
    int k0 = ch * 64, m0 = mb * 128;
#pragma unroll 4
    for (int i = 0; i < 32; ++i) {
        int idx = i * 256 + t;
        int k_l = idx & 63, r = idx >> 6;
        float v = E[(size_t)(m0 + r) * H + k0 + k_l];
        __nv_bfloat16 h = __float2bfloat16(v);
        __nv_bfloat16 l = __float2bfloat16(v - __bfloat162float(h));
        uint32_t off = SW128((uint32_t)(r * 128 + k_l * 2));
        *(__nv_bfloat16*)(esm + off) = h;
        *(__nv_bfloat16*)(esm + 16384 + off) = l;
    }
    __syncthreads();
    uint4* dst = (uint4*)(g_ET + ((size_t)mb * NCH + ch) * A_TILE);
    const uint4* s4 = (const uint4*)esm;
#pragma unroll
    for (int j = 0; j < 8; ++j) dst[t * 8 + j] = s4[t * 8 + j];
}

// ---------------- product kernel: swizzled (E[src] .* E[dst]) tiles ----------
__global__ __launch_bounds__(256) void product_pairs(
    const float* __restrict__ E, const int* __restrict__ rel)
{
    __shared__ __align__(16) char tile[A_TILE];
    __shared__ int ssrc[128], sdst[128];
    int t = threadIdx.x, bx = blockIdx.x, p0 = bx * 128;
    if (t < 128) {
        ssrc[t] = rel[(size_t)(p0 + t) * 2 + 0];
        sdst[t] = rel[(size_t)(p0 + t) * 2 + 1];
    }
    __syncthreads();
    int r = t >> 1, half = t & 1;
    const float* S = E + (size_t)ssrc[r] * H + half * 32;
    const float* D = E + (size_t)sdst[r] * H + half * 32;

    for (int ch = 0; ch < NCH; ++ch) {
        int k0 = ch * 64;
#pragma unroll
        for (int g = 0; g < 2; ++g) {
            float s[16], d[16], pr[16];
            *(float4*)(s)      = *(const float4*)(S + k0 + g * 16);
            *(float4*)(s + 4)  = *(const float4*)(S + k0 + g * 16 + 4);
            *(float4*)(s + 8)  = *(const float4*)(S + k0 + g * 16 + 8);
            *(float4*)(s + 12) = *(const float4*)(S + k0 + g * 16 + 12);
            *(float4*)(d)      = *(const float4*)(D + k0 + g * 16);
            *(float4*)(d + 4)  = *(const float4*)(D + k0 + g * 16 + 4);
            *(float4*)(d + 8)  = *(const float4*)(D + k0 + g * 16 + 8);
            *(float4*)(d + 12) = *(const float4*)(D + k0 + g * 16 + 12);
#pragma unroll
            for (int j = 0; j < 16; ++j) pr[j] = s[j] * d[j];
            uint32_t hi[8], lo[8];
            split8(pr, hi, lo);
            split8(pr + 8, hi + 4, lo + 4);
            uint32_t b0 = (uint32_t)(r * 128 + half * 64 + g * 32);
            *(uint4*)(tile + SW128(b0))              = make_uint4(hi[0], hi[1], hi[2], hi[3]);
            *(uint4*)(tile + SW128(b0 + 16))         = make_uint4(hi[4], hi[5], hi[6], hi[7]);
            *(uint4*)(tile + 16384 + SW128(b0))      = make_uint4(lo[0], lo[1], lo[2], lo[3]);
            *(uint4*)(tile + 16384 + SW128(b0 + 16)) = make_uint4(lo[4], lo[5], lo[6], lo[7]);
        }
        __syncthreads();
        uint4* dst = (uint4*)(g_P + ((size_t)bx * NCH + ch) * A_TILE + t * 128);
        const uint4* s4 = (const uint4*)(tile + t * 128);
#pragma unroll
        for (int j = 0; j < 8; ++j) dst[j] = s4[j];
        __syncthreads();
    }
}

// ---------------- UV GEMM: E @ [A|B] -----------------------------------------
__global__ void __launch_bounds__(256, 1) uv_mma_k() {
    extern __shared__ __align__(1024) char smem[];
    uint32_t sb = smem_u32(smem);
    int t = threadIdx.x, lane = t & 31, w = t >> 5;
    int wm = w >> 2, wn = w & 3;
    int mb = blockIdx.x, nb = blockIdx.y;

    float c[4][8][4];
#pragma unroll
    for (int a = 0; a < 4; ++a)
#pragma unroll
        for (int b = 0; b < 8; ++b)
#pragma unroll
            for (int d = 0; d < 4; ++d) c[a][b][d] = 0.f;

    gemm_mainloop(sb, g_ET + (size_t)mb * NCH * A_TILE,
                      g_BU + (size_t)nb * NCH * B_TILE, c, t, lane, wm, wn);

    float* Cs = (float*)smem;
    c_to_smem(Cs, c, lane, wm, wn);
    __syncthreads();

    int r = t >> 1, half = t & 1;
    float* dst = g_UV + (size_t)(mb * 128 + r) * (2 * H) + nb * 256 + half * 128;
    const float* srow = Cs + r * CSTRIDE + half * 128;
#pragma unroll
    for (int j = 0; j < 128; j += 4)
        *(float4*)(dst + j) = *(const float4*)(srow + j);
}

// ---------------- pair GEMM + fused epilogue ---------------------------------
__global__ void __launch_bounds__(256, 1) pair_mma_k(
    const int* __restrict__ rel, const float* __restrict__ b1,
    const float* __restrict__ W2)
{
    extern __shared__ __align__(1024) char smem[];
    uint32_t sb = smem_u32(smem);
    int t = threadIdx.x, lane = t & 31, w = t >> 5;
    int wm = w >> 2, wn = w & 3;
    int bx = blockIdx.x, by = blockIdx.y;
    int p0 = bx * 128;

    int* ssrc = (int*)(smem + SM_SRC);
    int* sdst = (int*)(smem + SM_DST);
    float* b1s = (float*)(smem + SM_B1);
    float* w2s = (float*)(smem + SM_W2);
    if (t < 128) {
        ssrc[t] = rel[(size_t)(p0 + t) * 2 + 0];
        sdst[t] = rel[(size_t)(p0 + t) * 2 + 1];
    }
    b1s[t] = b1[by * 256 + t];
    w2s[t] = W2[by * 256 + t];

    float c[4][8][4];
#pragma unroll
    for (int a = 0; a < 4; ++a)
#pragma unroll
        for (int b = 0; b < 8; ++b)
#pragma unroll
            for (int d = 0; d < 4; ++d) c[a][b][d] = 0.f;

    gemm_mainloop(sb, g_P + (size_t)bx * NCH * A_TILE,
                      g_BP + (size_t)by * NCH * B_TILE, c, t, lane, wm, wn);

    float* Cs = (float*)smem;
    c_to_smem(Cs, c, lane, wm, wn);
    __syncthreads();

    // epilogue: relu(C + U[src] + V[dst] + b1) . W2
    int r = t >> 1, half = t & 1;
    const float* crow = Cs + r * CSTRIDE + half * 128;
    const float* urow = g_UV + (size_t)ssrc[r] * (2 * H) + by * 256 + half * 128;
    const float* vrow = g_UV + (size_t)sdst[r] * (2 * H) + H + by * 256 + half * 128;
    float partial = 0.f;
#pragma unroll
    for (int j = 0; j < 128; j += 4) {
        float4 cc = *(const float4*)(crow + j);
        float4 u  = *(const float4*)(urow + j);
        float4 v  = *(const float4*)(vrow + j);
        int n = half * 128 + j;
        float h0 = cc.x + u.x + v.x + b1s[n + 0];
        float h1 = cc.y + u.y + v.y + b1s[n + 1];
        float h2 = cc.z + u.z + v.z + b1s[n + 2];
        float h3 = cc.w + u.w + v.w + b1s[n + 3];
        partial = fmaf(fmaxf(h0, 0.f), w2s[n + 0], partial);
        partial = fmaf(fmaxf(h1, 0.f), w2s[n + 1], partial);
        partial = fmaf(fmaxf(h2, 0.f), w2s[n + 2], partial);
        partial = fmaf(fmaxf(h3, 0.f), w2s[n + 3], partial);
    }
    partial += __shfl_xor_sync(0xffffffffu, partial, 1);
    if (half == 0)
        g_partial[(size_t)by * NPAIRS + p0 + r] = partial;
}

// ---------------- finalize ---------------------------------------------------
__global__ void finalize_kernel(const float* __restrict__ b2, float* __restrict__ out) {
    int p = blockIdx.x * blockDim.x + threadIdx.x;
    if (p >= NPAIRS) return;
    float z = g_partial[p] + g_partial[NPAIRS + p] + b2[0];
    out[p] = 1.f / (1.f + expf(-z));
}

// ---------------- launch -----------------------------------------------------
extern "C" void kernel_launch(void* const* d_in, const int* in_sizes, int n_in,
                              void* d_out, int out_size) {
    const float* E   = (const float*)d_in[1];
    const int*   rel = (const int*)  d_in[2];
    const float* W1  = (const float*)d_in[3];
    const float* b1  = (const float*)d_in[4];
    const float* W2  = (const float*)d_in[5];
    const float* b2  = (const float*)d_in[6];
    float* out = (float*)d_out;

    cudaFuncSetAttribute(prep_BP, cudaFuncAttributeMaxDynamicSharedMemorySize, B_TILE);
    cudaFuncSetAttribute(prep_BU, cudaFuncAttributeMaxDynamicSharedMemorySize, B_TILE);
    cudaFuncSetAttribute(uv_mma_k, cudaFuncAttributeMaxDynamicSharedMemorySize, SMEM_GEMM);
    cudaFuncSetAttribute(pair_mma_k, cudaFuncAttributeMaxDynamicSharedMemorySize, SMEM_GEMM);

    prep_BP<<<dim3(NCH, 2), 256, B_TILE>>>(W1);
    prep_BU<<<dim3(NCH, 4), 256, B_TILE>>>(W1);
    prep_ET<<<dim3(NCH, 128), 256>>>(E);
    product_pairs<<<1024, 256>>>(E, rel);
    uv_mma_k<<<dim3(128, 4), 256, SMEM_GEMM>>>();
    pair_mma_k<<<dim3(1024, 2), 256, SMEM_GEMM>>>(rel, b1, W2);
    finalize_kernel<<<NPAIRS / 256, 256>>>(b2, out);
}